// round 8
// baseline (speedup 1.0000x reference)
#include <cuda_runtime.h>
#include <cstdint>
#include <math.h>

#define NB 4
#define NC 64
#define HW 4096
#define BC (NB*NC)
#define NTILES 32   // 4096 keys / 128

// Scratch (allocation-free rule: __device__ globals)
__device__ float2   g_part[BC*4];         // per (bc, quarter) partial (sum, sumsq)
__device__ uint32_t g_wpk[24*8*64];       // w_qkv packed in tf32 B-frag order
__device__ uint32_t g_qb[NB*HW*32];       // Q bf16x2 token-major, x(0.125*log2e)
__device__ uint32_t g_kp[NB*NTILES*4096]; // K bf16 packed in m16n8k16 B-frag order
__device__ uint32_t g_vp[NB*NTILES*4096]; // V bf16 packed in m16n8k16 B-frag order

// ===========================================================================
// helpers
// ===========================================================================
__device__ __forceinline__ uint32_t smem_u32(const void* p) {
    uint32_t a;
    asm("{ .reg .u64 t; cvta.to.shared.u64 t, %1; cvt.u32.u64 %0, t; }" : "=r"(a) : "l"(p));
    return a;
}
__device__ __forceinline__ uint32_t bf16x2(float lo, float hi) {
    uint32_t r; asm("cvt.rn.bf16x2.f32 %0, %1, %2;" : "=r"(r) : "f"(hi), "f"(lo));
    return r;
}
__device__ __forceinline__ float tf32r(float x) {
    uint32_t u; asm("cvt.rna.tf32.f32 %0, %1;" : "=r"(u) : "f"(x));
    return __uint_as_float(u);
}
__device__ __forceinline__ uint32_t tf32u(float x) {
    uint32_t u; asm("cvt.rna.tf32.f32 %0, %1;" : "=r"(u) : "f"(x));
    return u;
}
__device__ __forceinline__ float ex2f(float x) {
    float r; asm("ex2.approx.f32 %0, %1;" : "=f"(r) : "f"(x));
    return r;
}
__device__ __forceinline__ void cp16(uint32_t dst, const void* src) {
    asm volatile("{ .reg .u64 g; cvta.to.global.u64 g, %1; "
                 "cp.async.cg.shared.global [%0], [g], 16; }"
                 :: "r"(dst), "l"(src) : "memory");
}
__device__ __forceinline__ void cp_commit() {
    asm volatile("cp.async.commit_group;" ::: "memory");
}
__device__ __forceinline__ void mma_bf16(float* d, const uint32_t* a, uint32_t b0, uint32_t b1) {
    asm volatile("mma.sync.aligned.m16n8k16.row.col.f32.bf16.bf16.f32 "
        "{%0,%1,%2,%3}, {%4,%5,%6,%7}, {%8,%9}, {%0,%1,%2,%3};"
        : "+f"(d[0]), "+f"(d[1]), "+f"(d[2]), "+f"(d[3])
        : "r"(a[0]), "r"(a[1]), "r"(a[2]), "r"(a[3]), "r"(b0), "r"(b1));
}
__device__ __forceinline__ void mma_tf32(float* d, const uint32_t* a, uint32_t b0, uint32_t b1) {
    asm volatile("mma.sync.aligned.m16n8k8.row.col.f32.tf32.tf32.f32 "
        "{%0,%1,%2,%3}, {%4,%5,%6,%7}, {%8,%9}, {%0,%1,%2,%3};"
        : "+f"(d[0]), "+f"(d[1]), "+f"(d[2]), "+f"(d[3])
        : "r"(a[0]), "r"(a[1]), "r"(a[2]), "r"(a[3]), "r"(b0), "r"(b1));
}
__device__ __forceinline__ void lds64(uint32_t addr, uint32_t& b0, uint32_t& b1) {
    asm volatile("ld.shared.v2.b32 {%0,%1}, [%2];" : "=r"(b0), "=r"(b1) : "r"(addr));
}

// ===========================================================================
// Kernel 1: instance-norm partial stats + one-time w_qkv pack.
// ===========================================================================
__global__ void stats_kernel(const float* __restrict__ x,
                             const float* __restrict__ w_qkv) {
    int bx = blockIdx.x;              // bc*4 + quarter
    int bc = bx >> 2, q = bx & 3;
    int t = threadIdx.x;              // 128
    const float4* p = (const float4*)(x + (size_t)bc * HW) + q * 256;
    float4 v1 = p[t], v2 = p[t + 128];
    float s  = v1.x + v1.y + v1.z + v1.w + v2.x + v2.y + v2.z + v2.w;
    float s2 = v1.x*v1.x + v1.y*v1.y + v1.z*v1.z + v1.w*v1.w
             + v2.x*v2.x + v2.y*v2.y + v2.z*v2.z + v2.w*v2.w;
    #pragma unroll
    for (int off = 16; off; off >>= 1) {
        s  += __shfl_xor_sync(0xffffffffu, s,  off);
        s2 += __shfl_xor_sync(0xffffffffu, s2, off);
    }
    __shared__ float sh[4], sh2[4];
    int w = t >> 5;
    if ((t & 31) == 0) { sh[w] = s; sh2[w] = s2; }
    __syncthreads();
    if (t == 0)
        g_part[bx] = make_float2(sh[0]+sh[1]+sh[2]+sh[3], sh2[0]+sh2[1]+sh2[2]+sh2[3]);

    if (bx < 192 && t < 64) {
        int nn24 = bx >> 3, kk = bx & 7;
        int no = t >> 3, ck = (t >> 1) & 3, h = t & 1;
        g_wpk[bx * 64 + t] = tf32u(w_qkv[(nn24*8 + no)*64 + kk*8 + ck + 4*h]);
    }
}

// ===========================================================================
// Kernel 2: normalize + qkv via tf32 mma.sync; pack Q/K/V bf16 fragments.
// ===========================================================================
#define QKV2_BIAS 0        // 192 floats
#define QKV2_MS   768      // mean[64], rstd[64]
#define QKV2_HS   1280     // [64][68] floats
#define QKV2_WPK  18688    // 48KB packed w
#define QKV2_ST   67840    // [192][65] floats
#define QKV2_SMEM 117760

__global__ __launch_bounds__(256, 1) void qkv_kernel(const float* __restrict__ x,
                           const float* __restrict__ b_qkv) {
    extern __shared__ __align__(16) char smem[];
    float* bias  = (float*)(smem + QKV2_BIAS);
    float* smean = (float*)(smem + QKV2_MS);
    float* srstd = smean + 64;
    float* hs    = (float*)(smem + QKV2_HS);   // stride 68
    float* st    = (float*)(smem + QKV2_ST);   // stride 65
    uint32_t sb = smem_u32(smem);
    int b  = blockIdx.y;
    int n0 = blockIdx.x << 6;
    int t = threadIdx.x;

    #pragma unroll
    for (int j = 0; j < 12; j++)
        cp16(sb + QKV2_WPK + t * 16 + j * 4096, (const char*)g_wpk + t * 16 + j * 4096);
    cp_commit();

    if (t < 48) ((float4*)bias)[t] = ((const float4*)b_qkv)[t];
    if (t < 64) {
        float s = 0.f, s2 = 0.f;
        #pragma unroll
        for (int q = 0; q < 4; q++) {
            float2 pp = g_part[(b * 64 + t) * 4 + q];
            s += pp.x; s2 += pp.y;
        }
        float m = s * (1.f / HW);
        float var = s2 * (1.f / HW) - m * m;
        smean[t] = m;
        srstd[t] = rsqrtf(var + 1e-5f);
    }
    __syncthreads();

    for (int i = t; i < 1024; i += 256) {
        int c = i >> 4, v4 = i & 15;
        float4 xv = ((const float4*)(x + ((size_t)(b * 64 + c) << 12) + n0))[v4];
        float m = smean[c], r = srstd[c];
        float* row = hs + c * 68 + v4 * 4;
        row[0] = tf32r((xv.x - m) * r); row[1] = tf32r((xv.y - m) * r);
        row[2] = tf32r((xv.z - m) * r); row[3] = tf32r((xv.w - m) * r);
    }
    asm volatile("cp.async.wait_group 0;" ::: "memory");
    __syncthreads();

    {
        int w = t >> 5, l = t & 31, g = l >> 2, tig = l & 3;
        int mt = w & 3, nh = w >> 2;
        int nbase = mt * 16 + g;
        const uint32_t* hsu = (const uint32_t*)hs;

        uint32_t af[8][4];
        #pragma unroll
        for (int kk = 0; kk < 8; kk++) {
            int c0 = kk * 8 + tig;
            af[kk][0] = hsu[c0 * 68 + nbase];
            af[kk][1] = hsu[c0 * 68 + nbase + 8];
            af[kk][2] = hsu[(c0 + 4) * 68 + nbase];
            af[kk][3] = hsu[(c0 + 4) * 68 + nbase + 8];
        }

        #pragma unroll
        for (int nn = 0; nn < 12; nn++) {
            float acc[4] = {0.f, 0.f, 0.f, 0.f};
            uint32_t wb = sb + QKV2_WPK + (uint32_t)((nh * 12 + nn) * 8) * 256;
            #pragma unroll
            for (int kk = 0; kk < 8; kk++) {
                uint32_t b0, b1;
                lds64(wb + kk * 256 + l * 8, b0, b1);
                mma_tf32(acc, af[kk], b0, b1);
            }
            int o = nh * 96 + nn * 8 + 2 * tig;
            float b0f = bias[o], b1f = bias[o + 1];
            st[o * 65 + nbase]           = acc[0] + b0f;
            st[(o + 1) * 65 + nbase]     = acc[1] + b1f;
            st[o * 65 + nbase + 8]       = acc[2] + b0f;
            st[(o + 1) * 65 + nbase + 8] = acc[3] + b1f;
        }
    }
    __syncthreads();

    int tile = n0 >> 7;
    int kb0  = n0 & 64;
    size_t tbase = (size_t)(b * 32 + tile) * 4096;

    // pack Q: token-major bf16x2, scale folds attention 0.125 AND log2(e)
    const float QS = 0.125f * 1.4426950408889634f;
    for (int i = t; i < 2048; i += 256) {
        int n = i >> 5, c2 = i & 31;
        float lo = st[(2*c2  ) * 65 + n] * QS;
        float hi = st[(2*c2+1) * 65 + n] * QS;
        g_qb[((size_t)b * HW + n0 + n) * 32 + c2] = bf16x2(lo, hi);
    }
    // pack K
    for (int i = t; i < 2048; i += 256) {
        int nn_l = i >> 8, kk = (i >> 6) & 3, g = (i >> 3) & 7, tig = (i >> 1) & 3, reg = i & 1;
        int n_l = nn_l * 8 + g;
        int c = kk * 16 + reg * 8 + tig * 2;
        float lo = st[(64 + c    ) * 65 + n_l];
        float hi = st[(64 + c + 1) * 65 + n_l];
        int nn_abs = (kb0 >> 3) + nn_l;
        g_kp[tbase + (nn_abs * 4 + kk) * 64 + g * 8 + tig * 2 + reg] = bf16x2(lo, hi);
    }
    // pack V
    for (int i = t; i < 2048; i += 256) {
        int nn = i >> 8, kk_l = (i >> 6) & 3, g = (i >> 3) & 7, tig = (i >> 1) & 3, reg = i & 1;
        int c = nn * 8 + g;
        int n_l = kk_l * 16 + reg * 8 + tig * 2;
        float lo = st[(128 + c) * 65 + n_l    ];
        float hi = st[(128 + c) * 65 + n_l + 1];
        int kk_abs = (kb0 >> 4) + kk_l;
        g_vp[tbase + (nn * 8 + kk_abs) * 64 + g * 8 + tig * 2 + reg] = bf16x2(lo, hi);
    }
}

// ===========================================================================
// Kernel 3: bf16 flash attention, 4 warps x M=32 (B-frags reused across 2
// M-blocks -> half the LDS traffic), ex2-softmax, fused out-proj + residual.
// CTA = (128 q-rows, batch), 128 threads.
// ===========================================================================
#define SMEM_ATT 65536   // [K0 16K][K1 16K][V0 16K][V1 16K]; reused by epilogue

__device__ __forceinline__ void stage_tile(uint32_t sb, int b, int tile, int buf, int t) {
    const char* ks = (const char*)g_kp + (((size_t)b * NTILES + tile) << 14);
    const char* vs = (const char*)g_vp + (((size_t)b * NTILES + tile) << 14);
    uint32_t kd = sb + ((uint32_t)buf << 14);
    uint32_t vd = sb + 32768u + ((uint32_t)buf << 14);
    #pragma unroll
    for (int j = 0; j < 8; j++) {
        cp16(kd + t * 16 + j * 2048, ks + t * 16 + j * 2048);
        cp16(vd + t * 16 + j * 2048, vs + t * 16 + j * 2048);
    }
}

__global__ __launch_bounds__(128, 1) void attn_mma_kernel(
        const float* __restrict__ x,
        const float* __restrict__ w_proj,
        const float* __restrict__ b_proj,
        float* __restrict__ out) {
    extern __shared__ __align__(128) char smem[];
    uint32_t sb = smem_u32(smem);
    const int t = threadIdx.x, w = t >> 5, l = t & 31;
    const int b = blockIdx.y, q0 = blockIdx.x << 7;
    const int g = l >> 2, tig = l & 3;

    // Q A-fragments for two 16-row M-blocks (warp owns 32 q rows)
    uint32_t qf[2][4][4];
    #pragma unroll
    for (int mt = 0; mt < 2; mt++) {
        const uint32_t* Qb = g_qb + ((size_t)b * HW + q0 + w * 32 + mt * 16) * 32;
        #pragma unroll
        for (int kk = 0; kk < 4; kk++) {
            qf[mt][kk][0] = Qb[(size_t)g       * 32 + 8*kk + tig];
            qf[mt][kk][1] = Qb[(size_t)(g + 8) * 32 + 8*kk + tig];
            qf[mt][kk][2] = Qb[(size_t)g       * 32 + 8*kk + tig + 4];
            qf[mt][kk][3] = Qb[(size_t)(g + 8) * 32 + 8*kk + tig + 4];
        }
    }

    stage_tile(sb, b, 0, 0, t); cp_commit();
    stage_tile(sb, b, 1, 1, t); cp_commit();

    float ls[2][2] = {{0.f, 0.f}, {0.f, 0.f}};
    float of[2][8][4];
    #pragma unroll
    for (int mt = 0; mt < 2; mt++)
        #pragma unroll
        for (int nn = 0; nn < 8; nn++)
            #pragma unroll
            for (int j = 0; j < 4; j++) of[mt][nn][j] = 0.f;

    for (int tile = 0; tile < NTILES; tile++) {
        int buf = tile & 1;
        if (tile < NTILES - 2) asm volatile("cp.async.wait_group 1;" ::: "memory");
        else                   asm volatile("cp.async.wait_group 0;" ::: "memory");
        __syncthreads();

        uint32_t kb = sb + ((uint32_t)buf << 14);
        uint32_t vb = sb + 32768u + ((uint32_t)buf << 14);

        #pragma unroll
        for (int h = 0; h < 2; h++) {
            // ---- S = Q K^T for 64-key half: each K frag feeds 2 mmas ----
            float sf[2][8][4];
            #pragma unroll
            for (int nn_l = 0; nn_l < 8; nn_l++) {
                #pragma unroll
                for (int mt = 0; mt < 2; mt++) {
                    sf[mt][nn_l][0] = 0.f; sf[mt][nn_l][1] = 0.f;
                    sf[mt][nn_l][2] = 0.f; sf[mt][nn_l][3] = 0.f;
                }
                int nn = 8 * h + nn_l;
                #pragma unroll
                for (int kk = 0; kk < 4; kk++) {
                    uint32_t b0, b1;
                    lds64(kb + ((uint32_t)(nn * 4 + kk) << 8) + ((uint32_t)l << 3), b0, b1);
                    mma_bf16(sf[0][nn_l], qf[0][kk], b0, b1);
                    mma_bf16(sf[1][nn_l], qf[1][kk], b0, b1);
                }
            }

            // ---- exp2 softmax accumulation (log2e folded into Q) ----
            #pragma unroll
            for (int mt = 0; mt < 2; mt++) {
                float s0 = 0.f, s1 = 0.f;
                #pragma unroll
                for (int nn = 0; nn < 8; nn++) {
                    sf[mt][nn][0] = ex2f(sf[mt][nn][0]);
                    sf[mt][nn][1] = ex2f(sf[mt][nn][1]);
                    sf[mt][nn][2] = ex2f(sf[mt][nn][2]);
                    sf[mt][nn][3] = ex2f(sf[mt][nn][3]);
                    s0 += sf[mt][nn][0] + sf[mt][nn][1];
                    s1 += sf[mt][nn][2] + sf[mt][nn][3];
                }
                ls[mt][0] += s0;
                ls[mt][1] += s1;
            }

            // ---- P: C-frag -> bf16 A-frag (index-identical) ----
            uint32_t pf[2][4][4];
            #pragma unroll
            for (int mt = 0; mt < 2; mt++)
                #pragma unroll
                for (int m = 0; m < 4; m++) {
                    pf[mt][m][0] = bf16x2(sf[mt][2*m  ][0], sf[mt][2*m  ][1]);
                    pf[mt][m][1] = bf16x2(sf[mt][2*m  ][2], sf[mt][2*m  ][3]);
                    pf[mt][m][2] = bf16x2(sf[mt][2*m+1][0], sf[mt][2*m+1][1]);
                    pf[mt][m][3] = bf16x2(sf[mt][2*m+1][2], sf[mt][2*m+1][3]);
                }

            // ---- O += P V : each V frag feeds 2 mmas ----
            #pragma unroll
            for (int nn = 0; nn < 8; nn++) {
                #pragma unroll
                for (int kk_l = 0; kk_l < 4; kk_l++) {
                    int kk = 4 * h + kk_l;
                    uint32_t b0, b1;
                    lds64(vb + ((uint32_t)(nn * 8 + kk) << 8) + ((uint32_t)l << 3), b0, b1);
                    mma_bf16(of[0][nn], pf[0][kk_l], b0, b1);
                    mma_bf16(of[1][nn], pf[1][kk_l], b0, b1);
                }
            }
        }

        __syncthreads();
        if (tile + 2 < NTILES) { stage_tile(sb, b, tile + 2, buf, t); cp_commit(); }
    }

    // row sums across the 4 lanes sharing a row
    #pragma unroll
    for (int mt = 0; mt < 2; mt++) {
        ls[mt][0] += __shfl_xor_sync(0xffffffffu, ls[mt][0], 1);
        ls[mt][0] += __shfl_xor_sync(0xffffffffu, ls[mt][0], 2);
        ls[mt][1] += __shfl_xor_sync(0xffffffffu, ls[mt][1], 1);
        ls[mt][1] += __shfl_xor_sync(0xffffffffu, ls[mt][1], 2);
    }

    // ========================================================================
    // Fused epilogue: normalize O -> smem, w_proj -> smem, GEMM + residual.
    // ========================================================================
    __syncthreads();
    float* Os  = (float*)smem;                  // [128][68]
    float* wsp = (float*)(smem + 36864);        // [64][64]
    #pragma unroll
    for (int mt = 0; mt < 2; mt++) {
        float i0 = 1.f / ls[mt][0], i1 = 1.f / ls[mt][1];
        int row0 = w * 32 + mt * 16 + g;
        #pragma unroll
        for (int nn = 0; nn < 8; nn++) {
            int col = nn * 8 + 2 * tig;
            float2* p0 = (float2*)(Os + row0 * 68 + col);
            float2* p1 = (float2*)(Os + (row0 + 8) * 68 + col);
            *p0 = make_float2(of[mt][nn][0] * i0, of[mt][nn][1] * i0);
            *p1 = make_float2(of[mt][nn][2] * i1, of[mt][nn][3] * i1);
        }
    }
    for (int i = t; i < 1024; i += 128)
        ((float4*)wsp)[i] = ((const float4*)w_proj)[i];
    __syncthreads();

    {
        int og2 = t >> 4;    // o = og2*8 + i, i<8
        int ng2 = t & 15;    // n = ng2 + 16*j, j<8
        float acc[8][8];
        #pragma unroll
        for (int i = 0; i < 8; i++)
            #pragma unroll
            for (int j = 0; j < 8; j++) acc[i][j] = 0.f;

        #pragma unroll 2
        for (int c4 = 0; c4 < 16; c4++) {
            float4 wv[8];
            #pragma unroll
            for (int i = 0; i < 8; i++)
                wv[i] = *(const float4*)(wsp + (og2 * 8 + i) * 64 + c4 * 4);
            #pragma unroll
            for (int j = 0; j < 8; j++) {
                float4 hv = *(const float4*)(Os + (ng2 + 16 * j) * 68 + c4 * 4);
                #pragma unroll
                for (int i = 0; i < 8; i++)
                    acc[i][j] += wv[i].x * hv.x + wv[i].y * hv.y
                               + wv[i].z * hv.z + wv[i].w * hv.w;
            }
        }

        #pragma unroll
        for (int i = 0; i < 8; i++) {
            int o = og2 * 8 + i;
            float bias = b_proj[o];
            const float* xr   = x   + (((size_t)(b * 64 + o)) << 12) + q0;
            float*       orow = out + (((size_t)(b * 64 + o)) << 12) + q0;
            #pragma unroll
            for (int j = 0; j < 8; j++) {
                int n = ng2 + 16 * j;
                orow[n] = xr[n] + acc[i][j] + bias;
            }
        }
    }
}

// ===========================================================================
extern "C" void kernel_launch(void* const* d_in, const int* in_sizes, int n_in,
                              void* d_out, int out_size) {
    const float* x      = (const float*)d_in[0];
    const float* w_qkv  = (const float*)d_in[1];
    const float* b_qkv  = (const float*)d_in[2];
    const float* w_proj = (const float*)d_in[3];
    const float* b_proj = (const float*)d_in[4];
    float* out = (float*)d_out;

    cudaFuncSetAttribute(qkv_kernel,
                         cudaFuncAttributeMaxDynamicSharedMemorySize, QKV2_SMEM);
    cudaFuncSetAttribute(attn_mma_kernel,
                         cudaFuncAttributeMaxDynamicSharedMemorySize, SMEM_ATT);

    stats_kernel<<<BC*4, 128>>>(x, w_qkv);
    qkv_kernel<<<dim3(64, NB), 256, QKV2_SMEM>>>(x, b_qkv);
    attn_mma_kernel<<<dim3(32, NB), 128, SMEM_ATT>>>(x, w_proj, b_proj, out);
}

// round 9
// speedup vs baseline: 1.1095x; 1.1095x over previous
#include <cuda_runtime.h>
#include <cstdint>
#include <math.h>

#define NB 4
#define NC 64
#define HW 4096
#define BC (NB*NC)
#define NTILES 32   // 4096 keys / 128

// Scratch (allocation-free rule: __device__ globals)
__device__ float2   g_part[BC*4];         // per (bc, quarter) partial (sum, sumsq)
__device__ uint32_t g_wpk[24*8*64];       // w_qkv packed in tf32 B-frag order
__device__ uint32_t g_wpj[8*8*64];        // w_proj packed in tf32 B-frag order
__device__ uint32_t g_qb[NB*HW*32];       // Q bf16x2 token-major, x(0.125*log2e)
__device__ uint32_t g_kp[NB*NTILES*4096]; // K bf16 packed in m16n8k16 B-frag order
__device__ uint32_t g_vp[NB*NTILES*4096]; // V bf16 packed in m16n8k16 B-frag order
__device__ float    g_po[2*NB*HW*64];     // partial O per key-half, token-major
__device__ float    g_ls[2*NB*HW];        // partial exp-sum per key-half

// ===========================================================================
// helpers
// ===========================================================================
__device__ __forceinline__ uint32_t smem_u32(const void* p) {
    uint32_t a;
    asm("{ .reg .u64 t; cvta.to.shared.u64 t, %1; cvt.u32.u64 %0, t; }" : "=r"(a) : "l"(p));
    return a;
}
__device__ __forceinline__ uint32_t bf16x2(float lo, float hi) {
    uint32_t r; asm("cvt.rn.bf16x2.f32 %0, %1, %2;" : "=r"(r) : "f"(hi), "f"(lo));
    return r;
}
__device__ __forceinline__ float tf32r(float x) {
    uint32_t u; asm("cvt.rna.tf32.f32 %0, %1;" : "=r"(u) : "f"(x));
    return __uint_as_float(u);
}
__device__ __forceinline__ uint32_t tf32u(float x) {
    uint32_t u; asm("cvt.rna.tf32.f32 %0, %1;" : "=r"(u) : "f"(x));
    return u;
}
__device__ __forceinline__ float ex2f(float x) {
    float r; asm("ex2.approx.f32 %0, %1;" : "=f"(r) : "f"(x));
    return r;
}
__device__ __forceinline__ void cp16(uint32_t dst, const void* src) {
    asm volatile("{ .reg .u64 g; cvta.to.global.u64 g, %1; "
                 "cp.async.cg.shared.global [%0], [g], 16; }"
                 :: "r"(dst), "l"(src) : "memory");
}
__device__ __forceinline__ void cp_commit() {
    asm volatile("cp.async.commit_group;" ::: "memory");
}
__device__ __forceinline__ void mma_bf16(float* d, const uint32_t* a, uint32_t b0, uint32_t b1) {
    asm volatile("mma.sync.aligned.m16n8k16.row.col.f32.bf16.bf16.f32 "
        "{%0,%1,%2,%3}, {%4,%5,%6,%7}, {%8,%9}, {%0,%1,%2,%3};"
        : "+f"(d[0]), "+f"(d[1]), "+f"(d[2]), "+f"(d[3])
        : "r"(a[0]), "r"(a[1]), "r"(a[2]), "r"(a[3]), "r"(b0), "r"(b1));
}
__device__ __forceinline__ void mma_tf32(float* d, const uint32_t* a, uint32_t b0, uint32_t b1) {
    asm volatile("mma.sync.aligned.m16n8k8.row.col.f32.tf32.tf32.f32 "
        "{%0,%1,%2,%3}, {%4,%5,%6,%7}, {%8,%9}, {%0,%1,%2,%3};"
        : "+f"(d[0]), "+f"(d[1]), "+f"(d[2]), "+f"(d[3])
        : "r"(a[0]), "r"(a[1]), "r"(a[2]), "r"(a[3]), "r"(b0), "r"(b1));
}
__device__ __forceinline__ void lds64(uint32_t addr, uint32_t& b0, uint32_t& b1) {
    asm volatile("ld.shared.v2.b32 {%0,%1}, [%2];" : "=r"(b0), "=r"(b1) : "r"(addr));
}

// ===========================================================================
// Kernel 1: instance-norm partial stats + one-time w_qkv / w_proj packs.
// ===========================================================================
__global__ void stats_kernel(const float* __restrict__ x,
                             const float* __restrict__ w_qkv,
                             const float* __restrict__ w_proj) {
    int bx = blockIdx.x;              // bc*4 + quarter
    int bc = bx >> 2, q = bx & 3;
    int t = threadIdx.x;              // 128
    const float4* p = (const float4*)(x + (size_t)bc * HW) + q * 256;
    float4 v1 = p[t], v2 = p[t + 128];
    float s  = v1.x + v1.y + v1.z + v1.w + v2.x + v2.y + v2.z + v2.w;
    float s2 = v1.x*v1.x + v1.y*v1.y + v1.z*v1.z + v1.w*v1.w
             + v2.x*v2.x + v2.y*v2.y + v2.z*v2.z + v2.w*v2.w;
    #pragma unroll
    for (int off = 16; off; off >>= 1) {
        s  += __shfl_xor_sync(0xffffffffu, s,  off);
        s2 += __shfl_xor_sync(0xffffffffu, s2, off);
    }
    __shared__ float sh[4], sh2[4];
    int w = t >> 5;
    if ((t & 31) == 0) { sh[w] = s; sh2[w] = s2; }
    __syncthreads();
    if (t == 0)
        g_part[bx] = make_float2(sh[0]+sh[1]+sh[2]+sh[3], sh2[0]+sh2[1]+sh2[2]+sh2[3]);

    if (bx < 192 && t < 64) {
        int nn24 = bx >> 3, kk = bx & 7;
        int no = t >> 3, ck = (t >> 1) & 3, h = t & 1;
        g_wpk[bx * 64 + t] = tf32u(w_qkv[(nn24*8 + no)*64 + kk*8 + ck + 4*h]);
    } else if (bx >= 192 && bx < 256 && t < 64) {
        int px = bx - 192;
        int nn8 = px >> 3, kk = px & 7;
        int no = t >> 3, ck = (t >> 1) & 3, h = t & 1;
        g_wpj[px * 64 + t] = tf32u(w_proj[(nn8*8 + no)*64 + kk*8 + ck + 4*h]);
    }
}

// ===========================================================================
// Kernel 2: normalize + qkv via tf32 mma.sync; pack Q/K/V bf16 fragments.
// (unchanged from round 7/8 working version)
// ===========================================================================
#define QKV2_BIAS 0        // 192 floats
#define QKV2_MS   768      // mean[64], rstd[64]
#define QKV2_HS   1280     // [64][68] floats
#define QKV2_WPK  18688    // 48KB packed w
#define QKV2_ST   67840    // [192][65] floats
#define QKV2_SMEM 117760

__global__ __launch_bounds__(256, 1) void qkv_kernel(const float* __restrict__ x,
                           const float* __restrict__ b_qkv) {
    extern __shared__ __align__(16) char smem[];
    float* bias  = (float*)(smem + QKV2_BIAS);
    float* smean = (float*)(smem + QKV2_MS);
    float* srstd = smean + 64;
    float* hs    = (float*)(smem + QKV2_HS);   // stride 68
    float* st    = (float*)(smem + QKV2_ST);   // stride 65
    uint32_t sb = smem_u32(smem);
    int b  = blockIdx.y;
    int n0 = blockIdx.x << 6;
    int t = threadIdx.x;

    #pragma unroll
    for (int j = 0; j < 12; j++)
        cp16(sb + QKV2_WPK + t * 16 + j * 4096, (const char*)g_wpk + t * 16 + j * 4096);
    cp_commit();

    if (t < 48) ((float4*)bias)[t] = ((const float4*)b_qkv)[t];
    if (t < 64) {
        float s = 0.f, s2 = 0.f;
        #pragma unroll
        for (int q = 0; q < 4; q++) {
            float2 pp = g_part[(b * 64 + t) * 4 + q];
            s += pp.x; s2 += pp.y;
        }
        float m = s * (1.f / HW);
        float var = s2 * (1.f / HW) - m * m;
        smean[t] = m;
        srstd[t] = rsqrtf(var + 1e-5f);
    }
    __syncthreads();

    for (int i = t; i < 1024; i += 256) {
        int c = i >> 4, v4 = i & 15;
        float4 xv = ((const float4*)(x + ((size_t)(b * 64 + c) << 12) + n0))[v4];
        float m = smean[c], r = srstd[c];
        float* row = hs + c * 68 + v4 * 4;
        row[0] = tf32r((xv.x - m) * r); row[1] = tf32r((xv.y - m) * r);
        row[2] = tf32r((xv.z - m) * r); row[3] = tf32r((xv.w - m) * r);
    }
    asm volatile("cp.async.wait_group 0;" ::: "memory");
    __syncthreads();

    {
        int w = t >> 5, l = t & 31, g = l >> 2, tig = l & 3;
        int mt = w & 3, nh = w >> 2;
        int nbase = mt * 16 + g;
        const uint32_t* hsu = (const uint32_t*)hs;

        uint32_t af[8][4];
        #pragma unroll
        for (int kk = 0; kk < 8; kk++) {
            int c0 = kk * 8 + tig;
            af[kk][0] = hsu[c0 * 68 + nbase];
            af[kk][1] = hsu[c0 * 68 + nbase + 8];
            af[kk][2] = hsu[(c0 + 4) * 68 + nbase];
            af[kk][3] = hsu[(c0 + 4) * 68 + nbase + 8];
        }

        #pragma unroll
        for (int nn = 0; nn < 12; nn++) {
            float acc[4] = {0.f, 0.f, 0.f, 0.f};
            uint32_t wb = sb + QKV2_WPK + (uint32_t)((nh * 12 + nn) * 8) * 256;
            #pragma unroll
            for (int kk = 0; kk < 8; kk++) {
                uint32_t b0, b1;
                lds64(wb + kk * 256 + l * 8, b0, b1);
                mma_tf32(acc, af[kk], b0, b1);
            }
            int o = nh * 96 + nn * 8 + 2 * tig;
            float b0f = bias[o], b1f = bias[o + 1];
            st[o * 65 + nbase]           = acc[0] + b0f;
            st[(o + 1) * 65 + nbase]     = acc[1] + b1f;
            st[o * 65 + nbase + 8]       = acc[2] + b0f;
            st[(o + 1) * 65 + nbase + 8] = acc[3] + b1f;
        }
    }
    __syncthreads();

    int tile = n0 >> 7;
    int kb0  = n0 & 64;
    size_t tbase = (size_t)(b * 32 + tile) * 4096;

    const float QS = 0.125f * 1.4426950408889634f;   // fold attn scale + log2(e)
    for (int i = t; i < 2048; i += 256) {
        int n = i >> 5, c2 = i & 31;
        float lo = st[(2*c2  ) * 65 + n] * QS;
        float hi = st[(2*c2+1) * 65 + n] * QS;
        g_qb[((size_t)b * HW + n0 + n) * 32 + c2] = bf16x2(lo, hi);
    }
    for (int i = t; i < 2048; i += 256) {
        int nn_l = i >> 8, kk = (i >> 6) & 3, g = (i >> 3) & 7, tig = (i >> 1) & 3, reg = i & 1;
        int n_l = nn_l * 8 + g;
        int c = kk * 16 + reg * 8 + tig * 2;
        float lo = st[(64 + c    ) * 65 + n_l];
        float hi = st[(64 + c + 1) * 65 + n_l];
        int nn_abs = (kb0 >> 3) + nn_l;
        g_kp[tbase + (nn_abs * 4 + kk) * 64 + g * 8 + tig * 2 + reg] = bf16x2(lo, hi);
    }
    for (int i = t; i < 2048; i += 256) {
        int nn = i >> 8, kk_l = (i >> 6) & 3, g = (i >> 3) & 7, tig = (i >> 1) & 3, reg = i & 1;
        int c = nn * 8 + g;
        int n_l = kk_l * 16 + reg * 8 + tig * 2;
        float lo = st[(128 + c) * 65 + n_l    ];
        float hi = st[(128 + c) * 65 + n_l + 1];
        int kk_abs = (kb0 >> 4) + kk_l;
        g_vp[tbase + (nn * 8 + kk_abs) * 64 + g * 8 + tig * 2 + reg] = bf16x2(lo, hi);
    }
}

// ===========================================================================
// Kernel 3: bf16 flash attention, split-K over keys.
// CTA = (256 q-rows, key-half, batch): 256 threads, 8 warps x M=32.
// Each K/V B-frag feeds 2 mmas. Writes partial unnormalized O + exp-sums.
// ===========================================================================
#define SMEM_ATT 65536   // [K0 16K][K1 16K][V0 16K][V1 16K]

__device__ __forceinline__ void stage_tile(uint32_t sb, int b, int tile, int buf, int t) {
    const char* ks = (const char*)g_kp + (((size_t)b * NTILES + tile) << 14);
    const char* vs = (const char*)g_vp + (((size_t)b * NTILES + tile) << 14);
    uint32_t kd = sb + ((uint32_t)buf << 14);
    uint32_t vd = sb + 32768u + ((uint32_t)buf << 14);
    #pragma unroll
    for (int j = 0; j < 4; j++) {
        cp16(kd + t * 16 + j * 4096, ks + t * 16 + j * 4096);
        cp16(vd + t * 16 + j * 4096, vs + t * 16 + j * 4096);
    }
}

__global__ __launch_bounds__(256, 1) void attn_mma_kernel() {
    extern __shared__ __align__(128) char smem[];
    uint32_t sb = smem_u32(smem);
    const int t = threadIdx.x, w = t >> 5, l = t & 31;
    const int b = blockIdx.y;
    const int q0 = (blockIdx.x >> 1) << 8;     // 256-query tile
    const int kh = blockIdx.x & 1;             // key half
    const int g = l >> 2, tig = l & 3;
    const int t0 = kh * 16;

    // Q A-fragments for two 16-row M-blocks (warp owns 32 q rows)
    uint32_t qf[2][4][4];
    #pragma unroll
    for (int mt = 0; mt < 2; mt++) {
        const uint32_t* Qb = g_qb + ((size_t)b * HW + q0 + w * 32 + mt * 16) * 32;
        #pragma unroll
        for (int kk = 0; kk < 4; kk++) {
            qf[mt][kk][0] = Qb[(size_t)g       * 32 + 8*kk + tig];
            qf[mt][kk][1] = Qb[(size_t)(g + 8) * 32 + 8*kk + tig];
            qf[mt][kk][2] = Qb[(size_t)g       * 32 + 8*kk + tig + 4];
            qf[mt][kk][3] = Qb[(size_t)(g + 8) * 32 + 8*kk + tig + 4];
        }
    }

    stage_tile(sb, b, t0, 0, t); cp_commit();
    stage_tile(sb, b, t0 + 1, 1, t); cp_commit();

    float ls[2][2] = {{0.f, 0.f}, {0.f, 0.f}};
    float of[2][8][4];
    #pragma unroll
    for (int mt = 0; mt < 2; mt++)
        #pragma unroll
        for (int nn = 0; nn < 8; nn++)
            #pragma unroll
            for (int j = 0; j < 4; j++) of[mt][nn][j] = 0.f;

    for (int i = 0; i < 16; i++) {
        int buf = i & 1;
        if (i < 14) asm volatile("cp.async.wait_group 1;" ::: "memory");
        else        asm volatile("cp.async.wait_group 0;" ::: "memory");
        __syncthreads();

        uint32_t kb = sb + ((uint32_t)buf << 14);
        uint32_t vb = sb + 32768u + ((uint32_t)buf << 14);

        #pragma unroll
        for (int h = 0; h < 2; h++) {
            // ---- S = Q K^T for 64-key half: each K frag feeds 2 mmas ----
            float sf[2][8][4];
            #pragma unroll
            for (int nn_l = 0; nn_l < 8; nn_l++) {
                #pragma unroll
                for (int mt = 0; mt < 2; mt++) {
                    sf[mt][nn_l][0] = 0.f; sf[mt][nn_l][1] = 0.f;
                    sf[mt][nn_l][2] = 0.f; sf[mt][nn_l][3] = 0.f;
                }
                int nn = 8 * h + nn_l;
                #pragma unroll
                for (int kk = 0; kk < 4; kk++) {
                    uint32_t b0, b1;
                    lds64(kb + ((uint32_t)(nn * 4 + kk) << 8) + ((uint32_t)l << 3), b0, b1);
                    mma_bf16(sf[0][nn_l], qf[0][kk], b0, b1);
                    mma_bf16(sf[1][nn_l], qf[1][kk], b0, b1);
                }
            }

            // ---- exp2 softmax accumulation ----
            #pragma unroll
            for (int mt = 0; mt < 2; mt++) {
                float s0 = 0.f, s1 = 0.f;
                #pragma unroll
                for (int nn = 0; nn < 8; nn++) {
                    sf[mt][nn][0] = ex2f(sf[mt][nn][0]);
                    sf[mt][nn][1] = ex2f(sf[mt][nn][1]);
                    sf[mt][nn][2] = ex2f(sf[mt][nn][2]);
                    sf[mt][nn][3] = ex2f(sf[mt][nn][3]);
                    s0 += sf[mt][nn][0] + sf[mt][nn][1];
                    s1 += sf[mt][nn][2] + sf[mt][nn][3];
                }
                ls[mt][0] += s0;
                ls[mt][1] += s1;
            }

            // ---- P: C-frag -> bf16 A-frag (index-identical) ----
            uint32_t pf[2][4][4];
            #pragma unroll
            for (int mt = 0; mt < 2; mt++)
                #pragma unroll
                for (int m = 0; m < 4; m++) {
                    pf[mt][m][0] = bf16x2(sf[mt][2*m  ][0], sf[mt][2*m  ][1]);
                    pf[mt][m][1] = bf16x2(sf[mt][2*m  ][2], sf[mt][2*m  ][3]);
                    pf[mt][m][2] = bf16x2(sf[mt][2*m+1][0], sf[mt][2*m+1][1]);
                    pf[mt][m][3] = bf16x2(sf[mt][2*m+1][2], sf[mt][2*m+1][3]);
                }

            // ---- O += P V : each V frag feeds 2 mmas ----
            #pragma unroll
            for (int nn = 0; nn < 8; nn++) {
                #pragma unroll
                for (int kk_l = 0; kk_l < 4; kk_l++) {
                    int kk = 4 * h + kk_l;
                    uint32_t b0, b1;
                    lds64(vb + ((uint32_t)(nn * 8 + kk) << 8) + ((uint32_t)l << 3), b0, b1);
                    mma_bf16(of[0][nn], pf[0][kk_l], b0, b1);
                    mma_bf16(of[1][nn], pf[1][kk_l], b0, b1);
                }
            }
        }

        __syncthreads();
        if (i + 2 < 16) { stage_tile(sb, b, t0 + i + 2, buf, t); cp_commit(); }
    }

    // row sums across the 4 lanes sharing a row
    #pragma unroll
    for (int mt = 0; mt < 2; mt++) {
        ls[mt][0] += __shfl_xor_sync(0xffffffffu, ls[mt][0], 1);
        ls[mt][0] += __shfl_xor_sync(0xffffffffu, ls[mt][0], 2);
        ls[mt][1] += __shfl_xor_sync(0xffffffffu, ls[mt][1], 1);
        ls[mt][1] += __shfl_xor_sync(0xffffffffu, ls[mt][1], 2);
    }

    // ---- write partial O (unnormalized) + lsums ----
    size_t pbase = ((size_t)(kh * NB + b) * HW + q0 + w * 32) * 64;
    #pragma unroll
    for (int mt = 0; mt < 2; mt++) {
        int row0 = mt * 16 + g;
        #pragma unroll
        for (int nn = 0; nn < 8; nn++) {
            int col = nn * 8 + 2 * tig;
            *(float2*)(g_po + pbase + (size_t)row0 * 64 + col) =
                make_float2(of[mt][nn][0], of[mt][nn][1]);
            *(float2*)(g_po + pbase + (size_t)(row0 + 8) * 64 + col) =
                make_float2(of[mt][nn][2], of[mt][nn][3]);
        }
        if (tig == 0) {
            size_t lbase = (size_t)(kh * NB + b) * HW + q0 + w * 32 + mt * 16;
            g_ls[lbase + g]     = ls[mt][0];
            g_ls[lbase + g + 8] = ls[mt][1];
        }
    }
}

// ===========================================================================
// Kernel 4: merge key-halves + normalize + tf32-mma out-proj + bias + residual.
// Grid (64, NB), 128 threads / 4 warps (warp = 16-token M-tile).
// ===========================================================================
#define MP_LS   0        // 64 floats inv-sums (pad to 256B)
#define MP_OS   256      // [64][68] floats
#define MP_ST   17664    // [64][68] floats
#define MP_WPJ  35072    // 16KB packed w_proj
#define MP_SMEM 51456

__global__ __launch_bounds__(128, 1) void mproj_kernel(
        const float* __restrict__ x,
        const float* __restrict__ b_proj,
        float* __restrict__ out) {
    extern __shared__ __align__(16) char smem[];
    float* lsinv = (float*)(smem + MP_LS);
    float* Os    = (float*)(smem + MP_OS);   // stride 68
    float* st    = (float*)(smem + MP_ST);   // stride 68
    uint32_t sb = smem_u32(smem);
    int b  = blockIdx.y;
    int n0 = blockIdx.x << 6;
    int t = threadIdx.x;

    #pragma unroll
    for (int j = 0; j < 8; j++)
        cp16(sb + MP_WPJ + t * 16 + j * 2048, (const char*)g_wpj + t * 16 + j * 2048);
    cp_commit();

    if (t < 64)
        lsinv[t] = 1.f / (g_ls[(size_t)b * HW + n0 + t] +
                          g_ls[(size_t)(NB + b) * HW + n0 + t]);
    __syncthreads();

    // merge + normalize + tf32-round into Os[n][c]
    for (int i = t; i < 1024; i += 128) {
        int n = i >> 4, c4 = i & 15;
        const float4 a = *(const float4*)(g_po + ((size_t)b * HW + n0 + n) * 64 + c4 * 4);
        const float4 c = *(const float4*)(g_po + ((size_t)(NB + b) * HW + n0 + n) * 64 + c4 * 4);
        float inv = lsinv[n];
        float* row = Os + n * 68 + c4 * 4;
        row[0] = tf32r((a.x + c.x) * inv); row[1] = tf32r((a.y + c.y) * inv);
        row[2] = tf32r((a.z + c.z) * inv); row[3] = tf32r((a.w + c.w) * inv);
    }
    asm volatile("cp.async.wait_group 0;" ::: "memory");
    __syncthreads();

    // tf32 mma: out_st[n][o] = sum_c Os[n][c] * w_proj[o][c]
    {
        int w = t >> 5, l = t & 31, g = l >> 2, tig = l & 3;
        int nbase = w * 16 + g;
        const uint32_t* Osu = (const uint32_t*)Os;

        uint32_t af[8][4];
        #pragma unroll
        for (int kk = 0; kk < 8; kk++) {
            int c0 = kk * 8 + tig;
            af[kk][0] = Osu[(size_t)nbase * 68 + c0];
            af[kk][1] = Osu[(size_t)(nbase + 8) * 68 + c0];
            af[kk][2] = Osu[(size_t)nbase * 68 + c0 + 4];
            af[kk][3] = Osu[(size_t)(nbase + 8) * 68 + c0 + 4];
        }

        #pragma unroll
        for (int nn = 0; nn < 8; nn++) {
            float acc[4] = {0.f, 0.f, 0.f, 0.f};
            uint32_t wb = sb + MP_WPJ + (uint32_t)(nn * 8) * 256;
            #pragma unroll
            for (int kk = 0; kk < 8; kk++) {
                uint32_t b0, b1;
                lds64(wb + kk * 256 + l * 8, b0, b1);
                mma_tf32(acc, af[kk], b0, b1);
            }
            int o = nn * 8 + 2 * tig;
            st[o * 68 + nbase]           = acc[0];
            st[(o + 1) * 68 + nbase]     = acc[1];
            st[o * 68 + nbase + 8]       = acc[2];
            st[(o + 1) * 68 + nbase + 8] = acc[3];
        }
    }
    __syncthreads();

    // write out = x + bias + st, coalesced float4 rows
    for (int i = t; i < 1024; i += 128) {
        int o = i >> 4, v4 = i & 15;
        float bias = b_proj[o];
        size_t idx4 = (((size_t)(b * 64 + o) << 12) + n0) / 4 + v4;
        float4 xv = ((const float4*)x)[idx4];
        const float* row = st + o * 68 + v4 * 4;
        ((float4*)out)[idx4] = make_float4(xv.x + row[0] + bias, xv.y + row[1] + bias,
                                           xv.z + row[2] + bias, xv.w + row[3] + bias);
    }
}

// ===========================================================================
extern "C" void kernel_launch(void* const* d_in, const int* in_sizes, int n_in,
                              void* d_out, int out_size) {
    const float* x      = (const float*)d_in[0];
    const float* w_qkv  = (const float*)d_in[1];
    const float* b_qkv  = (const float*)d_in[2];
    const float* w_proj = (const float*)d_in[3];
    const float* b_proj = (const float*)d_in[4];
    float* out = (float*)d_out;

    cudaFuncSetAttribute(qkv_kernel,
                         cudaFuncAttributeMaxDynamicSharedMemorySize, QKV2_SMEM);
    cudaFuncSetAttribute(attn_mma_kernel,
                         cudaFuncAttributeMaxDynamicSharedMemorySize, SMEM_ATT);
    cudaFuncSetAttribute(mproj_kernel,
                         cudaFuncAttributeMaxDynamicSharedMemorySize, MP_SMEM);

    stats_kernel<<<BC*4, 128>>>(x, w_qkv, w_proj);
    qkv_kernel<<<dim3(64, NB), 256, QKV2_SMEM>>>(x, b_qkv);
    attn_mma_kernel<<<dim3(32, NB), 256, SMEM_ATT>>>();
    mproj_kernel<<<dim3(64, NB), 128, MP_SMEM>>>(x, b_proj, out);
}

// round 11
// speedup vs baseline: 1.1465x; 1.0333x over previous
#include <cuda_runtime.h>
#include <cstdint>
#include <math.h>

#define NB 4
#define NC 64
#define HW 4096
#define BC (NB*NC)
#define NTILES 32   // 4096 keys / 128

// Scratch (allocation-free rule: __device__ globals)
__device__ float2   g_part[BC*4];         // per (bc, quarter) partial (sum, sumsq)
__device__ uint32_t g_wpk[24*8*64];       // w_qkv packed in tf32 B-frag order
__device__ uint32_t g_wpj[8*8*64];        // w_proj packed in tf32 B-frag order
__device__ uint32_t g_qb[NB*HW*32];       // Q bf16x2 token-major, x(0.125*log2e)
__device__ uint32_t g_kp[NB*NTILES*4096]; // K bf16 packed in m16n8k16 B-frag order
__device__ uint32_t g_vp[NB*NTILES*4096]; // V bf16 packed in m16n8k16 B-frag order
__device__ float    g_po[2*NB*HW*64];     // partial O per key-half, token-major
__device__ float    g_ls[2*NB*HW];        // partial exp-sum per key-half

// ===========================================================================
// helpers
// ===========================================================================
__device__ __forceinline__ uint32_t smem_u32(const void* p) {
    uint32_t a;
    asm("{ .reg .u64 t; cvta.to.shared.u64 t, %1; cvt.u32.u64 %0, t; }" : "=r"(a) : "l"(p));
    return a;
}
__device__ __forceinline__ uint32_t bf16x2(float lo, float hi) {
    uint32_t r; asm("cvt.rn.bf16x2.f32 %0, %1, %2;" : "=r"(r) : "f"(hi), "f"(lo));
    return r;
}
__device__ __forceinline__ float tf32r(float x) {
    uint32_t u; asm("cvt.rna.tf32.f32 %0, %1;" : "=r"(u) : "f"(x));
    return __uint_as_float(u);
}
__device__ __forceinline__ uint32_t tf32u(float x) {
    uint32_t u; asm("cvt.rna.tf32.f32 %0, %1;" : "=r"(u) : "f"(x));
    return u;
}
__device__ __forceinline__ float ex2f(float x) {
    float r; asm("ex2.approx.f32 %0, %1;" : "=f"(r) : "f"(x));
    return r;
}
__device__ __forceinline__ void cp16(uint32_t dst, const void* src) {
    asm volatile("{ .reg .u64 g; cvta.to.global.u64 g, %1; "
                 "cp.async.cg.shared.global [%0], [g], 16; }"
                 :: "r"(dst), "l"(src) : "memory");
}
__device__ __forceinline__ void cp_commit() {
    asm volatile("cp.async.commit_group;" ::: "memory");
}
__device__ __forceinline__ void mma_bf16(float* d, const uint32_t* a, uint32_t b0, uint32_t b1) {
    asm volatile("mma.sync.aligned.m16n8k16.row.col.f32.bf16.bf16.f32 "
        "{%0,%1,%2,%3}, {%4,%5,%6,%7}, {%8,%9}, {%0,%1,%2,%3};"
        : "+f"(d[0]), "+f"(d[1]), "+f"(d[2]), "+f"(d[3])
        : "r"(a[0]), "r"(a[1]), "r"(a[2]), "r"(a[3]), "r"(b0), "r"(b1));
}
__device__ __forceinline__ void mma_tf32(float* d, const uint32_t* a, uint32_t b0, uint32_t b1) {
    asm volatile("mma.sync.aligned.m16n8k8.row.col.f32.tf32.tf32.f32 "
        "{%0,%1,%2,%3}, {%4,%5,%6,%7}, {%8,%9}, {%0,%1,%2,%3};"
        : "+f"(d[0]), "+f"(d[1]), "+f"(d[2]), "+f"(d[3])
        : "r"(a[0]), "r"(a[1]), "r"(a[2]), "r"(a[3]), "r"(b0), "r"(b1));
}
__device__ __forceinline__ void lds64(uint32_t addr, uint32_t& b0, uint32_t& b1) {
    asm volatile("ld.shared.v2.b32 {%0,%1}, [%2];" : "=r"(b0), "=r"(b1) : "r"(addr));
}

// ===========================================================================
// Kernel 1: instance-norm partial stats + one-time w_qkv / w_proj packs.
// ===========================================================================
__global__ void stats_kernel(const float* __restrict__ x,
                             const float* __restrict__ w_qkv,
                             const float* __restrict__ w_proj) {
    int bx = blockIdx.x;              // bc*4 + quarter
    int bc = bx >> 2, q = bx & 3;
    int t = threadIdx.x;              // 128
    const float4* p = (const float4*)(x + (size_t)bc * HW) + q * 256;
    float4 v1 = p[t], v2 = p[t + 128];
    float s  = v1.x + v1.y + v1.z + v1.w + v2.x + v2.y + v2.z + v2.w;
    float s2 = v1.x*v1.x + v1.y*v1.y + v1.z*v1.z + v1.w*v1.w
             + v2.x*v2.x + v2.y*v2.y + v2.z*v2.z + v2.w*v2.w;
    #pragma unroll
    for (int off = 16; off; off >>= 1) {
        s  += __shfl_xor_sync(0xffffffffu, s,  off);
        s2 += __shfl_xor_sync(0xffffffffu, s2, off);
    }
    __shared__ float sh[4], sh2[4];
    int w = t >> 5;
    if ((t & 31) == 0) { sh[w] = s; sh2[w] = s2; }
    __syncthreads();
    if (t == 0)
        g_part[bx] = make_float2(sh[0]+sh[1]+sh[2]+sh[3], sh2[0]+sh2[1]+sh2[2]+sh2[3]);

    if (bx < 192 && t < 64) {
        int nn24 = bx >> 3, kk = bx & 7;
        int no = t >> 3, ck = (t >> 1) & 3, h = t & 1;
        g_wpk[bx * 64 + t] = tf32u(w_qkv[(nn24*8 + no)*64 + kk*8 + ck + 4*h]);
    } else if (bx >= 192 && bx < 256 && t < 64) {
        int px = bx - 192;
        int nn8 = px >> 3, kk = px & 7;
        int no = t >> 3, ck = (t >> 1) & 3, h = t & 1;
        g_wpj[px * 64 + t] = tf32u(w_proj[(nn8*8 + no)*64 + kk*8 + ck + 4*h]);
    }
}

// ===========================================================================
// Kernel 2: normalize + qkv via tf32 mma.sync; pack Q/K/V bf16 fragments.
// ===========================================================================
#define QKV2_BIAS 0        // 192 floats
#define QKV2_MS   768      // mean[64], rstd[64]
#define QKV2_HS   1280     // [64][68] floats
#define QKV2_WPK  18688    // 48KB packed w
#define QKV2_ST   67840    // [192][65] floats
#define QKV2_SMEM 117760

__global__ __launch_bounds__(256, 1) void qkv_kernel(const float* __restrict__ x,
                           const float* __restrict__ b_qkv) {
    extern __shared__ __align__(16) char smem[];
    float* bias  = (float*)(smem + QKV2_BIAS);
    float* smean = (float*)(smem + QKV2_MS);
    float* srstd = smean + 64;
    float* hs    = (float*)(smem + QKV2_HS);   // stride 68
    float* st    = (float*)(smem + QKV2_ST);   // stride 65
    uint32_t sb = smem_u32(smem);
    int b  = blockIdx.y;
    int n0 = blockIdx.x << 6;
    int t = threadIdx.x;

    #pragma unroll
    for (int j = 0; j < 12; j++)
        cp16(sb + QKV2_WPK + t * 16 + j * 4096, (const char*)g_wpk + t * 16 + j * 4096);
    cp_commit();

    if (t < 48) ((float4*)bias)[t] = ((const float4*)b_qkv)[t];
    if (t < 64) {
        float s = 0.f, s2 = 0.f;
        #pragma unroll
        for (int q = 0; q < 4; q++) {
            float2 pp = g_part[(b * 64 + t) * 4 + q];
            s += pp.x; s2 += pp.y;
        }
        float m = s * (1.f / HW);
        float var = s2 * (1.f / HW) - m * m;
        smean[t] = m;
        srstd[t] = rsqrtf(var + 1e-5f);
    }
    __syncthreads();

    for (int i = t; i < 1024; i += 256) {
        int c = i >> 4, v4 = i & 15;
        float4 xv = ((const float4*)(x + ((size_t)(b * 64 + c) << 12) + n0))[v4];
        float m = smean[c], r = srstd[c];
        float* row = hs + c * 68 + v4 * 4;
        row[0] = tf32r((xv.x - m) * r); row[1] = tf32r((xv.y - m) * r);
        row[2] = tf32r((xv.z - m) * r); row[3] = tf32r((xv.w - m) * r);
    }
    asm volatile("cp.async.wait_group 0;" ::: "memory");
    __syncthreads();

    {
        int w = t >> 5, l = t & 31, g = l >> 2, tig = l & 3;
        int mt = w & 3, nh = w >> 2;
        int nbase = mt * 16 + g;
        const uint32_t* hsu = (const uint32_t*)hs;

        uint32_t af[8][4];
        #pragma unroll
        for (int kk = 0; kk < 8; kk++) {
            int c0 = kk * 8 + tig;
            af[kk][0] = hsu[c0 * 68 + nbase];
            af[kk][1] = hsu[c0 * 68 + nbase + 8];
            af[kk][2] = hsu[(c0 + 4) * 68 + nbase];
            af[kk][3] = hsu[(c0 + 4) * 68 + nbase + 8];
        }

        #pragma unroll
        for (int nn = 0; nn < 12; nn++) {
            float acc[4] = {0.f, 0.f, 0.f, 0.f};
            uint32_t wb = sb + QKV2_WPK + (uint32_t)((nh * 12 + nn) * 8) * 256;
            #pragma unroll
            for (int kk = 0; kk < 8; kk++) {
                uint32_t b0, b1;
                lds64(wb + kk * 256 + l * 8, b0, b1);
                mma_tf32(acc, af[kk], b0, b1);
            }
            int o = nh * 96 + nn * 8 + 2 * tig;
            float b0f = bias[o], b1f = bias[o + 1];
            st[o * 65 + nbase]           = acc[0] + b0f;
            st[(o + 1) * 65 + nbase]     = acc[1] + b1f;
            st[o * 65 + nbase + 8]       = acc[2] + b0f;
            st[(o + 1) * 65 + nbase + 8] = acc[3] + b1f;
        }
    }
    __syncthreads();

    int tile = n0 >> 7;
    int kb0  = n0 & 64;
    size_t tbase = (size_t)(b * 32 + tile) * 4096;

    const float QS = 0.125f * 1.4426950408889634f;   // fold attn scale + log2(e)
    for (int i = t; i < 2048; i += 256) {
        int n = i >> 5, c2 = i & 31;
        float lo = st[(2*c2  ) * 65 + n] * QS;
        float hi = st[(2*c2+1) * 65 + n] * QS;
        g_qb[((size_t)b * HW + n0 + n) * 32 + c2] = bf16x2(lo, hi);
    }
    for (int i = t; i < 2048; i += 256) {
        int nn_l = i >> 8, kk = (i >> 6) & 3, g = (i >> 3) & 7, tig = (i >> 1) & 3, reg = i & 1;
        int n_l = nn_l * 8 + g;
        int c = kk * 16 + reg * 8 + tig * 2;
        float lo = st[(64 + c    ) * 65 + n_l];
        float hi = st[(64 + c + 1) * 65 + n_l];
        int nn_abs = (kb0 >> 3) + nn_l;
        g_kp[tbase + (nn_abs * 4 + kk) * 64 + g * 8 + tig * 2 + reg] = bf16x2(lo, hi);
    }
    for (int i = t; i < 2048; i += 256) {
        int nn = i >> 8, kk_l = (i >> 6) & 3, g = (i >> 3) & 7, tig = (i >> 1) & 3, reg = i & 1;
        int c = nn * 8 + g;
        int n_l = kk_l * 16 + reg * 8 + tig * 2;
        float lo = st[(128 + c) * 65 + n_l    ];
        float hi = st[(128 + c) * 65 + n_l + 1];
        int kk_abs = (kb0 >> 4) + kk_l;
        g_vp[tbase + (nn * 8 + kk_abs) * 64 + g * 8 + tig * 2 + reg] = bf16x2(lo, hi);
    }
}

// ===========================================================================
// Kernel 3: bf16 flash attention, split-K over keys.
// CTA = (256 q-rows, key-half, batch): 256 threads, 8 warps x M=32.
// ===========================================================================
#define SMEM_ATT 65536   // [K0 16K][K1 16K][V0 16K][V1 16K]

__device__ __forceinline__ void stage_tile(uint32_t sb, int b, int tile, int buf, int t) {
    const char* ks = (const char*)g_kp + (((size_t)b * NTILES + tile) << 14);
    const char* vs = (const char*)g_vp + (((size_t)b * NTILES + tile) << 14);
    uint32_t kd = sb + ((uint32_t)buf << 14);
    uint32_t vd = sb + 32768u + ((uint32_t)buf << 14);
    #pragma unroll
    for (int j = 0; j < 4; j++) {
        cp16(kd + t * 16 + j * 4096, ks + t * 16 + j * 4096);
        cp16(vd + t * 16 + j * 4096, vs + t * 16 + j * 4096);
    }
}

__global__ __launch_bounds__(256, 1) void attn_mma_kernel() {
    extern __shared__ __align__(128) char smem[];
    uint32_t sb = smem_u32(smem);
    const int t = threadIdx.x, w = t >> 5, l = t & 31;
    const int b = blockIdx.y;
    const int q0 = (blockIdx.x >> 1) << 8;     // 256-query tile
    const int kh = blockIdx.x & 1;             // key half
    const int g = l >> 2, tig = l & 3;
    const int t0 = kh * 16;

    uint32_t qf[2][4][4];
    #pragma unroll
    for (int mt = 0; mt < 2; mt++) {
        const uint32_t* Qb = g_qb + ((size_t)b * HW + q0 + w * 32 + mt * 16) * 32;
        #pragma unroll
        for (int kk = 0; kk < 4; kk++) {
            qf[mt][kk][0] = Qb[(size_t)g       * 32 + 8*kk + tig];
            qf[mt][kk][1] = Qb[(size_t)(g + 8) * 32 + 8*kk + tig];
            qf[mt][kk][2] = Qb[(size_t)g       * 32 + 8*kk + tig + 4];
            qf[mt][kk][3] = Qb[(size_t)(g + 8) * 32 + 8*kk + tig + 4];
        }
    }

    stage_tile(sb, b, t0, 0, t); cp_commit();
    stage_tile(sb, b, t0 + 1, 1, t); cp_commit();

    float ls[2][2] = {{0.f, 0.f}, {0.f, 0.f}};
    float of[2][8][4];
    #pragma unroll
    for (int mt = 0; mt < 2; mt++)
        #pragma unroll
        for (int nn = 0; nn < 8; nn++)
            #pragma unroll
            for (int j = 0; j < 4; j++) of[mt][nn][j] = 0.f;

    for (int i = 0; i < 16; i++) {
        int buf = i & 1;
        if (i < 14) asm volatile("cp.async.wait_group 1;" ::: "memory");
        else        asm volatile("cp.async.wait_group 0;" ::: "memory");
        __syncthreads();

        uint32_t kb = sb + ((uint32_t)buf << 14);
        uint32_t vb = sb + 32768u + ((uint32_t)buf << 14);

        #pragma unroll
        for (int h = 0; h < 2; h++) {
            float sf[2][8][4];
            #pragma unroll
            for (int nn_l = 0; nn_l < 8; nn_l++) {
                #pragma unroll
                for (int mt = 0; mt < 2; mt++) {
                    sf[mt][nn_l][0] = 0.f; sf[mt][nn_l][1] = 0.f;
                    sf[mt][nn_l][2] = 0.f; sf[mt][nn_l][3] = 0.f;
                }
                int nn = 8 * h + nn_l;
                #pragma unroll
                for (int kk = 0; kk < 4; kk++) {
                    uint32_t b0, b1;
                    lds64(kb + ((uint32_t)(nn * 4 + kk) << 8) + ((uint32_t)l << 3), b0, b1);
                    mma_bf16(sf[0][nn_l], qf[0][kk], b0, b1);
                    mma_bf16(sf[1][nn_l], qf[1][kk], b0, b1);
                }
            }

            #pragma unroll
            for (int mt = 0; mt < 2; mt++) {
                float s0 = 0.f, s1 = 0.f;
                #pragma unroll
                for (int nn = 0; nn < 8; nn++) {
                    sf[mt][nn][0] = ex2f(sf[mt][nn][0]);
                    sf[mt][nn][1] = ex2f(sf[mt][nn][1]);
                    sf[mt][nn][2] = ex2f(sf[mt][nn][2]);
                    sf[mt][nn][3] = ex2f(sf[mt][nn][3]);
                    s0 += sf[mt][nn][0] + sf[mt][nn][1];
                    s1 += sf[mt][nn][2] + sf[mt][nn][3];
                }
                ls[mt][0] += s0;
                ls[mt][1] += s1;
            }

            uint32_t pf[2][4][4];
            #pragma unroll
            for (int mt = 0; mt < 2; mt++)
                #pragma unroll
                for (int m = 0; m < 4; m++) {
                    pf[mt][m][0] = bf16x2(sf[mt][2*m  ][0], sf[mt][2*m  ][1]);
                    pf[mt][m][1] = bf16x2(sf[mt][2*m  ][2], sf[mt][2*m  ][3]);
                    pf[mt][m][2] = bf16x2(sf[mt][2*m+1][0], sf[mt][2*m+1][1]);
                    pf[mt][m][3] = bf16x2(sf[mt][2*m+1][2], sf[mt][2*m+1][3]);
                }

            #pragma unroll
            for (int nn = 0; nn < 8; nn++) {
                #pragma unroll
                for (int kk_l = 0; kk_l < 4; kk_l++) {
                    int kk = 4 * h + kk_l;
                    uint32_t b0, b1;
                    lds64(vb + ((uint32_t)(nn * 8 + kk) << 8) + ((uint32_t)l << 3), b0, b1);
                    mma_bf16(of[0][nn], pf[0][kk_l], b0, b1);
                    mma_bf16(of[1][nn], pf[1][kk_l], b0, b1);
                }
            }
        }

        __syncthreads();
        if (i + 2 < 16) { stage_tile(sb, b, t0 + i + 2, buf, t); cp_commit(); }
    }

    #pragma unroll
    for (int mt = 0; mt < 2; mt++) {
        ls[mt][0] += __shfl_xor_sync(0xffffffffu, ls[mt][0], 1);
        ls[mt][0] += __shfl_xor_sync(0xffffffffu, ls[mt][0], 2);
        ls[mt][1] += __shfl_xor_sync(0xffffffffu, ls[mt][1], 1);
        ls[mt][1] += __shfl_xor_sync(0xffffffffu, ls[mt][1], 2);
    }

    size_t pbase = ((size_t)(kh * NB + b) * HW + q0 + w * 32) * 64;
    #pragma unroll
    for (int mt = 0; mt < 2; mt++) {
        int row0 = mt * 16 + g;
        #pragma unroll
        for (int nn = 0; nn < 8; nn++) {
            int col = nn * 8 + 2 * tig;
            *(float2*)(g_po + pbase + (size_t)row0 * 64 + col) =
                make_float2(of[mt][nn][0], of[mt][nn][1]);
            *(float2*)(g_po + pbase + (size_t)(row0 + 8) * 64 + col) =
                make_float2(of[mt][nn][2], of[mt][nn][3]);
        }
        if (tig == 0) {
            size_t lbase = (size_t)(kh * NB + b) * HW + q0 + w * 32 + mt * 16;
            g_ls[lbase + g]     = ls[mt][0];
            g_ls[lbase + g + 8] = ls[mt][1];
        }
    }
}

// ===========================================================================
// Kernel 4: merge key-halves + normalize + tf32-mma out-proj + bias + residual.
// Grid (32, NB), 256 threads / 8 warps, 128 tokens per block -> 2 CTAs/SM.
// ===========================================================================
#define MP_LS   0        // 128 floats inv-sums
#define MP_OS   512      // [128][68] floats = 34816
#define MP_ST   35328    // [64][132] floats = 33792
#define MP_WPJ  69120    // 16KB packed w_proj
#define MP_SMEM 85504

__global__ __launch_bounds__(256, 2) void mproj_kernel(
        const float* __restrict__ x,
        const float* __restrict__ b_proj,
        float* __restrict__ out) {
    extern __shared__ __align__(16) char smem[];
    float* lsinv = (float*)(smem + MP_LS);
    float* Os    = (float*)(smem + MP_OS);   // stride 68
    float* st    = (float*)(smem + MP_ST);   // stride 132
    uint32_t sb = smem_u32(smem);
    int b  = blockIdx.y;
    int n0 = blockIdx.x << 7;    // 128 tokens
    int t = threadIdx.x;

    #pragma unroll
    for (int j = 0; j < 4; j++)
        cp16(sb + MP_WPJ + t * 16 + j * 4096, (const char*)g_wpj + t * 16 + j * 4096);
    cp_commit();

    if (t < 128)
        lsinv[t] = 1.f / (g_ls[(size_t)b * HW + n0 + t] +
                          g_ls[(size_t)(NB + b) * HW + n0 + t]);
    __syncthreads();

    // merge + normalize + tf32-round into Os[n][c]  (16 indep float4 loads/thread)
    for (int i = t; i < 2048; i += 256) {
        int n = i >> 4, c4 = i & 15;
        const float4 a = *(const float4*)(g_po + ((size_t)b * HW + n0 + n) * 64 + c4 * 4);
        const float4 c = *(const float4*)(g_po + ((size_t)(NB + b) * HW + n0 + n) * 64 + c4 * 4);
        float inv = lsinv[n];
        float* row = Os + n * 68 + c4 * 4;
        row[0] = tf32r((a.x + c.x) * inv); row[1] = tf32r((a.y + c.y) * inv);
        row[2] = tf32r((a.z + c.z) * inv); row[3] = tf32r((a.w + c.w) * inv);
    }
    asm volatile("cp.async.wait_group 0;" ::: "memory");
    __syncthreads();

    // tf32 mma: st[o][n] = sum_c Os[n][c] * w_proj[o][c]; warp = 16-token M-tile
    {
        int w = t >> 5, l = t & 31, g = l >> 2, tig = l & 3;
        int nbase = w * 16 + g;
        const uint32_t* Osu = (const uint32_t*)Os;

        uint32_t af[8][4];
        #pragma unroll
        for (int kk = 0; kk < 8; kk++) {
            int c0 = kk * 8 + tig;
            af[kk][0] = Osu[(size_t)nbase * 68 + c0];
            af[kk][1] = Osu[(size_t)(nbase + 8) * 68 + c0];
            af[kk][2] = Osu[(size_t)nbase * 68 + c0 + 4];
            af[kk][3] = Osu[(size_t)(nbase + 8) * 68 + c0 + 4];
        }

        #pragma unroll
        for (int nn = 0; nn < 8; nn++) {
            float acc[4] = {0.f, 0.f, 0.f, 0.f};
            uint32_t wb = sb + MP_WPJ + (uint32_t)(nn * 8) * 256;
            #pragma unroll
            for (int kk = 0; kk < 8; kk++) {
                uint32_t b0, b1;
                lds64(wb + kk * 256 + l * 8, b0, b1);
                mma_tf32(acc, af[kk], b0, b1);
            }
            int o = nn * 8 + 2 * tig;
            st[o * 132 + nbase]           = acc[0];
            st[(o + 1) * 132 + nbase]     = acc[1];
            st[o * 132 + nbase + 8]       = acc[2];
            st[(o + 1) * 132 + nbase + 8] = acc[3];
        }
    }
    __syncthreads();

    // write out = x + bias + st, coalesced float4 rows (64 o x 128 n)
    for (int i = t; i < 2048; i += 256) {
        int o = i >> 5, v4 = i & 31;
        float bias = b_proj[o];
        size_t idx4 = (((size_t)(b * 64 + o) << 12) + n0) / 4 + v4;
        float4 xv = ((const float4*)x)[idx4];
        const float* row = st + o * 132 + v4 * 4;
        ((float4*)out)[idx4] = make_float4(xv.x + row[0] + bias, xv.y + row[1] + bias,
                                           xv.z + row[2] + bias, xv.w + row[3] + bias);
    }
}

// ===========================================================================
extern "C" void kernel_launch(void* const* d_in, const int* in_sizes, int n_in,
                              void* d_out, int out_size) {
    const float* x      = (const float*)d_in[0];
    const float* w_qkv  = (const float*)d_in[1];
    const float* b_qkv  = (const float*)d_in[2];
    const float* w_proj = (const float*)d_in[3];
    const float* b_proj = (const float*)d_in[4];
    float* out = (float*)d_out;

    cudaFuncSetAttribute(qkv_kernel,
                         cudaFuncAttributeMaxDynamicSharedMemorySize, QKV2_SMEM);
    cudaFuncSetAttribute(attn_mma_kernel,
                         cudaFuncAttributeMaxDynamicSharedMemorySize, SMEM_ATT);
    cudaFuncSetAttribute(mproj_kernel,
                         cudaFuncAttributeMaxDynamicSharedMemorySize, MP_SMEM);

    stats_kernel<<<BC*4, 128>>>(x, w_qkv, w_proj);
    qkv_kernel<<<dim3(64, NB), 256, QKV2_SMEM>>>(x, b_qkv);
    attn_mma_kernel<<<dim3(32, NB), 256, SMEM_ATT>>>();
    mproj_kernel<<<dim3(32, NB), 256, MP_SMEM>>>(x, b_proj, out);
}